// round 17
// baseline (speedup 1.0000x reference)
#include <cuda_runtime.h>
#include <cuda_bf16.h>
#include <cstdint>
#include <math.h>

#define D_MODEL 1024
#define NHEADS  16
#define BB      4
#define SS      2048
#define BS      (BB*SS)          // 8192
#define PI_F    3.14159265358979323846f
#define NSLICE  32

// ---------------- scratch (static device globals, no allocation) ----------------
__device__ float g_part[NSLICE][5][BB*D_MODEL];
__device__ float g_sums[5][BB*D_MODEL];
__device__ __nv_bfloat16 g_attb[BS*D_MODEL];
__device__ __nv_bfloat16 g_xb[BS*D_MODEL];
__device__ __nv_bfloat16 g_wb[3*D_MODEL*D_MODEL];
__device__ __nv_bfloat16 g_qb[BS*D_MODEL];
__device__ __nv_bfloat16 g_kb[BS*D_MODEL];
__device__ __nv_bfloat16 g_vb[BS*D_MODEL];

// ================= helpers =================
__device__ __forceinline__ uint32_t smem_to_u32(const void* p) {
    uint32_t a;
    asm("{ .reg .u64 t; cvta.to.shared.u64 t, %1; cvt.u32.u64 %0, t; }" : "=r"(a) : "l"(p));
    return a;
}
__device__ __forceinline__ uint32_t sw128(uint32_t o) { return o ^ ((o >> 3) & 0x70); }

__device__ __forceinline__ void ldm_x4(uint32_t& r0, uint32_t& r1, uint32_t& r2, uint32_t& r3, uint32_t addr) {
    asm volatile("ldmatrix.sync.aligned.m8n8.x4.shared.b16 {%0,%1,%2,%3}, [%4];"
                 : "=r"(r0), "=r"(r1), "=r"(r2), "=r"(r3) : "r"(addr));
}
__device__ __forceinline__ void ldm_x4t(uint32_t& r0, uint32_t& r1, uint32_t& r2, uint32_t& r3, uint32_t addr) {
    asm volatile("ldmatrix.sync.aligned.m8n8.x4.trans.shared.b16 {%0,%1,%2,%3}, [%4];"
                 : "=r"(r0), "=r"(r1), "=r"(r2), "=r"(r3) : "r"(addr));
}
__device__ __forceinline__ void mma_bf16(float* c, uint32_t a0, uint32_t a1, uint32_t a2, uint32_t a3,
                                         uint32_t b0, uint32_t b1) {
    asm volatile("mma.sync.aligned.m16n8k16.row.col.f32.bf16.bf16.f32 "
                 "{%0,%1,%2,%3}, {%4,%5,%6,%7}, {%8,%9}, {%0,%1,%2,%3};"
                 : "+f"(c[0]), "+f"(c[1]), "+f"(c[2]), "+f"(c[3])
                 : "r"(a0), "r"(a1), "r"(a2), "r"(a3), "r"(b0), "r"(b1));
}
// pack: low16 = lo, high16 = hi
__device__ __forceinline__ uint32_t pack_bf16(float hi, float lo) {
    uint32_t d;
    asm("cvt.rn.bf16x2.f32 %0, %1, %2;" : "=r"(d) : "f"(hi), "f"(lo));
    return d;
}
#define CP_ASYNC16(dst, src) \
    asm volatile("cp.async.cg.shared.global [%0], [%1], 16;" :: "r"(dst), "l"(src))
#define CP_COMMIT  asm volatile("cp.async.commit_group;" ::: "memory")
#define CP_WAIT0   asm volatile("cp.async.wait_group 0;" ::: "memory")
#define CP_WAIT1   asm volatile("cp.async.wait_group 1;" ::: "memory")

// ---------------- 0) fp32 -> bf16 conversion (3 weight matrices, one launch) ----------------
__global__ __launch_bounds__(256) void cvtw_kernel(const float* __restrict__ w0,
                                                   const float* __restrict__ w1,
                                                   const float* __restrict__ w2,
                                                   __nv_bfloat16* __restrict__ out) {
    int z = blockIdx.y;
    const float* in = (z == 0) ? w0 : ((z == 1) ? w1 : w2);
    int i = (blockIdx.x * 256 + threadIdx.x) * 8;
    float4 v0 = *(const float4*)(in + i);
    float4 v1 = *(const float4*)(in + i + 4);
    uint4 u;
    __nv_bfloat162 p;
    p = __floats2bfloat162_rn(v0.x, v0.y); u.x = *(uint32_t*)&p;
    p = __floats2bfloat162_rn(v0.z, v0.w); u.y = *(uint32_t*)&p;
    p = __floats2bfloat162_rn(v1.x, v1.y); u.z = *(uint32_t*)&p;
    p = __floats2bfloat162_rn(v1.z, v1.w); u.w = *(uint32_t*)&p;
    *(uint4*)(out + (size_t)z * D_MODEL * D_MODEL + i) = u;
}

// ---------------- 1) DSP reductions + fused x->bf16 ----------------
__global__ __launch_bounds__(256) void dsp_sums_kernel(const float* __restrict__ x) {
    __shared__ float cs_c[SS/NSLICE], cs_s[SS/NSLICE];
    int d  = blockIdx.x * 256 + threadIdx.x;
    int b  = blockIdx.y;
    int t0 = blockIdx.z * (SS / NSLICE);
    const float w = 2.f * PI_F / (float)SS;
    if (threadIdx.x < SS/NSLICE) {
        float sn, cn;
        sincosf(w * (float)(t0 + threadIdx.x), &sn, &cn);
        cs_c[threadIdx.x] = cn; cs_s[threadIdx.x] = sn;
    }
    __syncthreads();

    float s0 = 0.f, a1 = 0.f, b1 = 0.f, a2 = 0.f, b2 = 0.f;
    size_t xoff = ((size_t)b * SS + t0) * D_MODEL + d;
    const float* xp = x + xoff;
    __nv_bfloat16* xb = g_xb + xoff;
    #pragma unroll 8
    for (int k = 0; k < SS/NSLICE; ++k) {
        float xv = xp[(size_t)k * D_MODEL];
        xb[(size_t)k * D_MODEL] = __float2bfloat16(xv);
        float c1 = cs_c[k], s1 = cs_s[k];
        float c2 = 2.f * c1 * c1 - 1.f;
        float s2 = 2.f * s1 * c1;
        s0 += xv;
        a1 += xv * c1;  b1 += xv * s1;
        a2 += xv * c2;  b2 += xv * s2;
    }
    int bd = b * D_MODEL + d;
    g_part[blockIdx.z][0][bd] = s0;
    g_part[blockIdx.z][1][bd] = a1;
    g_part[blockIdx.z][2][bd] = b1;
    g_part[blockIdx.z][3][bd] = a2;
    g_part[blockIdx.z][4][bd] = b2;
}

__global__ void combine_sums_kernel() {
    int i = blockIdx.x * 256 + threadIdx.x;
    if (i >= 5 * BB * D_MODEL) return;
    float v = 0.f;
    #pragma unroll
    for (int s = 0; s < NSLICE; ++s)
        v += (&g_part[s][0][0])[i];
    (&g_sums[0][0])[i] = v;
}

// ---------------- 2) bf16 mma.sync GEMM: 256x128 tile, 512 threads, 3-stage cp.async ----------------
// Higher arithmetic intensity per staged slab (48KB -> 1024 warp-MMAs) to cut
// cp.async/LSU pressure per MMA. 16 warps (4m x 4n grid), warp tile 64x32
// (identical per-warp datapath to the validated version). 1 CTA/SM, full RF.
#define GEMM_SMEM_BYTES (3*49152)
#define GEMM_STAGE      49152

__global__ __launch_bounds__(512, 1) void gemm_mma_kernel(
    const __nv_bfloat16* __restrict__ xb,
    const __nv_bfloat16* __restrict__ w0, const __nv_bfloat16* __restrict__ w1,
    const __nv_bfloat16* __restrict__ w2,
    const float* __restrict__ bq, const float* __restrict__ bk, const float* __restrict__ bv,
    __nv_bfloat16* __restrict__ c0, __nv_bfloat16* __restrict__ c1, __nv_bfloat16* __restrict__ c2)
{
    extern __shared__ char smem[];
    uint32_t su = smem_to_u32(smem);
    int tid = threadIdx.x;
    int wid = tid >> 5, lane = tid & 31;
    int wm = wid >> 2, wn = wid & 3;        // warp grid 4(m) x 4(n)

    int z = blockIdx.z;
    const __nv_bfloat16* W = (z == 0) ? w0 : ((z == 1) ? w1 : w2);
    const float* bias = (z == 0) ? bq : ((z == 1) ? bk : bv);
    __nv_bfloat16* C = (z == 0) ? c0 : ((z == 1) ? c1 : c2);
    float outsc = (z == 0) ? 0.125f : 1.0f;   // fold 1/sqrt(dk) into q
    int n0 = blockIdx.x * 128, m0 = blockIdx.y * 256;

    // A staging: 256 rows x 128B; thread covers 64B (4 x 16B)
    int srow = tid >> 1, shalf = tid & 1;
    const char* Ag = (const char*)(xb + (size_t)(m0 + srow) * 1024 + shalf * 32);
    uint32_t soA[4];
    #pragma unroll
    for (int j = 0; j < 4; ++j)
        soA[j] = sw128((uint32_t)(srow * 128 + shalf * 64 + j * 16));
    // B staging: 128 rows x 128B; thread covers 32B (2 x 16B)
    int brow = tid >> 2, bq4 = tid & 3;
    const char* Bg = (const char*)(W + (size_t)(n0 + brow) * 1024 + bq4 * 16);
    uint32_t soB[2];
    #pragma unroll
    for (int j = 0; j < 2; ++j)
        soB[j] = sw128((uint32_t)(brow * 128 + bq4 * 32 + j * 16));

    int a_lrow = lane & 15;
    int a_koff = (lane >> 4) * 16;
    // paired B-fragment ldmatrix.x4 lane mapping:
    int b_rbase = ((lane >> 4) & 1) * 8 + (lane & 7);
    int b_coff  = ((lane >> 3) & 1) * 16;

    float acc[4][4][4];
    #pragma unroll
    for (int i = 0; i < 4; ++i)
        #pragma unroll
        for (int j = 0; j < 4; ++j)
            #pragma unroll
            for (int r = 0; r < 4; ++r) acc[i][j][r] = 0.f;

    // prologue: stage slabs 0,1 into stages 0,1
    #pragma unroll
    for (int s = 0; s < 2; ++s) {
        uint32_t sAu = su + s * GEMM_STAGE, sBu = sAu + 32768;
        #pragma unroll
        for (int j = 0; j < 4; ++j)
            CP_ASYNC16(sAu + soA[j], Ag + (size_t)s * 128 + j * 16);
        #pragma unroll
        for (int j = 0; j < 2; ++j)
            CP_ASYNC16(sBu + soB[j], Bg + (size_t)s * 128 + j * 16);
        CP_COMMIT;
    }

    int bc = 0, bp = 2;   // compute / prefetch stage indices (rotate mod 3)
    for (int slab = 0; slab < 16; ++slab) {
        if (slab == 15) { CP_WAIT0; } else { CP_WAIT1; }
        __syncthreads();
        if (slab < 14) {
            uint32_t sAu = su + bp * GEMM_STAGE, sBu = sAu + 32768;
            const char* as = Ag + (size_t)(slab + 2) * 128;
            const char* bs = Bg + (size_t)(slab + 2) * 128;
            #pragma unroll
            for (int j = 0; j < 4; ++j)
                CP_ASYNC16(sAu + soA[j], as + j * 16);
            #pragma unroll
            for (int j = 0; j < 2; ++j)
                CP_ASYNC16(sBu + soB[j], bs + j * 16);
            CP_COMMIT;
        }

        uint32_t sAu = su + bc * GEMM_STAGE;
        uint32_t sBu = sAu + 32768;
        #pragma unroll
        for (int ks = 0; ks < 4; ++ks) {
            uint32_t af[4][4], bfr[4][2];
            #pragma unroll
            for (int mi = 0; mi < 4; ++mi) {
                int row = wm * 64 + mi * 16 + a_lrow;
                uint32_t off = (uint32_t)(row * 128 + ks * 32 + a_koff);
                ldm_x4(af[mi][0], af[mi][1], af[mi][2], af[mi][3], sAu + sw128(off));
            }
            #pragma unroll
            for (int pr = 0; pr < 2; ++pr) {
                uint32_t off = (uint32_t)((wn * 32 + pr * 16 + b_rbase) * 128 + ks * 32 + b_coff);
                ldm_x4(bfr[2*pr][0], bfr[2*pr][1], bfr[2*pr+1][0], bfr[2*pr+1][1],
                       sBu + sw128(off));
            }
            #pragma unroll
            for (int mi = 0; mi < 4; ++mi)
                #pragma unroll
                for (int ni = 0; ni < 4; ++ni)
                    mma_bf16(acc[mi][ni], af[mi][0], af[mi][1], af[mi][2], af[mi][3],
                             bfr[ni][0], bfr[ni][1]);
        }
        bc = (bc == 2) ? 0 : bc + 1;
        bp = (bp == 2) ? 0 : bp + 1;
    }

    // ---- epilogue: bias + scale + bf16 store ----
    int g = lane >> 2, tg = lane & 3;
    #pragma unroll
    for (int mi = 0; mi < 4; ++mi) {
        int row = m0 + wm * 64 + mi * 16 + g;
        #pragma unroll
        for (int ni = 0; ni < 4; ++ni) {
            int col = n0 + wn * 32 + ni * 8 + 2 * tg;
            float2 bsv = *(const float2*)&bias[col];
            uint32_t p0 = pack_bf16((acc[mi][ni][1] + bsv.y) * outsc, (acc[mi][ni][0] + bsv.x) * outsc);
            uint32_t p1 = pack_bf16((acc[mi][ni][3] + bsv.y) * outsc, (acc[mi][ni][2] + bsv.x) * outsc);
            *(uint32_t*)&C[(size_t)row * 1024 + col]       = p0;
            *(uint32_t*)&C[(size_t)(row + 8) * 1024 + col] = p1;
        }
    }
}

// ---------------- 3) bf16 mma.sync flash attention (no-max softmax, 128-key tiles, 2 CTAs/SM) ----------------
#define ATT_SMEM_BYTES (80*1024)

__global__ __launch_bounds__(256, 2) void attn_mma_kernel() {
    extern __shared__ char sm8[];
    uint32_t su = smem_to_u32(sm8);
    int tid = threadIdx.x, wid = tid >> 5, lane = tid & 31;
    int g = lane >> 2, tg = lane & 3;
    int q0 = blockIdx.x * 128, bh = blockIdx.y;
    size_t base = ((size_t)(bh >> 4)) * SS * D_MODEL + (size_t)(bh & 15) * 64;

    // Q tile (128 rows x 64 bf16 = 128B rows), SW128
    {
        int row = tid >> 1, half = tid & 1;
        const uint4* src = (const uint4*)&g_qb[base + (size_t)(q0 + row) * D_MODEL];
        #pragma unroll
        for (int j = 0; j < 4; ++j) {
            uint32_t off = (uint32_t)(row * 128 + half * 64 + j * 16);
            *(uint4*)(sm8 + sw128(off)) = src[half * 4 + j];
        }
    }
    // K/V staging addresses: each thread covers rows row4 and row4+64, 2 x 16B each
    int row4 = tid >> 2, c4 = tid & 3;
    uint32_t soff[2][2];
    #pragma unroll
    for (int j2 = 0; j2 < 2; ++j2)
        #pragma unroll
        for (int j = 0; j < 2; ++j)
            soff[j2][j] = sw128((uint32_t)((row4 + 64 * j2) * 128 + (c4 + 4 * j) * 16));

    // tile 0 via cp.async (128 keys)
    {
        uint32_t dK = su + 16384, dV = dK + 16384;
        #pragma unroll
        for (int j2 = 0; j2 < 2; ++j2) {
            const char* ks = (const char*)&g_kb[base + (size_t)(row4 + 64 * j2) * D_MODEL];
            const char* vs = (const char*)&g_vb[base + (size_t)(row4 + 64 * j2) * D_MODEL];
            #pragma unroll
            for (int j = 0; j < 2; ++j) {
                CP_ASYNC16(dK + soff[j2][j], ks + (c4 + 4 * j) * 16);
                CP_ASYNC16(dV + soff[j2][j], vs + (c4 + 4 * j) * 16);
            }
        }
        CP_COMMIT;
    }
    CP_WAIT0;
    __syncthreads();

    // Q fragments (held in registers for all key tiles)
    int a_lrow = lane & 15, a_koff = (lane >> 4) * 16;
    uint32_t qf[4][4];
    #pragma unroll
    for (int kf = 0; kf < 4; ++kf) {
        uint32_t off = (uint32_t)((wid * 16 + a_lrow) * 128 + kf * 32 + a_koff);
        ldm_x4(qf[kf][0], qf[kf][1], qf[kf][2], qf[kf][3], su + sw128(off));
    }
    // paired K-fragment ldmatrix.x4 lane mapping
    int b_rbase = ((lane >> 4) & 1) * 8 + (lane & 7);
    int b_coff  = ((lane >> 3) & 1) * 16;
    int t_lrow = lane & 15, t_hi = (lane >> 4) * 16;

    float l0 = 0.f, l1 = 0.f;
    float O[8][4];
    #pragma unroll
    for (int nd = 0; nd < 8; ++nd)
        #pragma unroll
        for (int r = 0; r < 4; ++r) O[nd][r] = 0.f;

    for (int kt = 0; kt < SS/128; ++kt) {
        int buf = kt & 1;
        if (kt < SS/128 - 1) {
            int k0n = (kt + 1) * 128;
            uint32_t dK = su + 16384 + (buf ^ 1) * 32768;
            uint32_t dV = dK + 16384;
            #pragma unroll
            for (int j2 = 0; j2 < 2; ++j2) {
                const char* ks = (const char*)&g_kb[base + (size_t)(k0n + row4 + 64 * j2) * D_MODEL];
                const char* vs = (const char*)&g_vb[base + (size_t)(k0n + row4 + 64 * j2) * D_MODEL];
                #pragma unroll
                for (int j = 0; j < 2; ++j) {
                    CP_ASYNC16(dK + soff[j2][j], ks + (c4 + 4 * j) * 16);
                    CP_ASYNC16(dV + soff[j2][j], vs + (c4 + 4 * j) * 16);
                }
            }
            CP_COMMIT;
        }

        #pragma unroll
        for (int h = 0; h < 2; ++h) {
            uint32_t suK = su + 16384 + buf * 32768 + h * 8192;
            uint32_t suV = su + 16384 + buf * 32768 + 16384 + h * 8192;

            // S = Q K^T (K frags via paired ldmatrix.x4)
            float s[8][4];
            #pragma unroll
            for (int ni = 0; ni < 8; ++ni)
                #pragma unroll
                for (int r = 0; r < 4; ++r) s[ni][r] = 0.f;
            #pragma unroll
            for (int kf = 0; kf < 4; ++kf) {
                uint32_t bk[8][2];
                #pragma unroll
                for (int pr = 0; pr < 4; ++pr) {
                    uint32_t off = (uint32_t)((pr * 16 + b_rbase) * 128 + kf * 32 + b_coff);
                    ldm_x4(bk[2*pr][0], bk[2*pr][1], bk[2*pr+1][0], bk[2*pr+1][1],
                           suK + sw128(off));
                }
                #pragma unroll
                for (int ni = 0; ni < 8; ++ni)
                    mma_bf16(s[ni], qf[kf][0], qf[kf][1], qf[kf][2], qf[kf][3],
                             bk[ni][0], bk[ni][1]);
            }

            // p = exp(s), accumulate partial row sums
            float rs0 = 0.f, rs1 = 0.f;
            #pragma unroll
            for (int ni = 0; ni < 8; ++ni) {
                s[ni][0] = __expf(s[ni][0]);
                s[ni][1] = __expf(s[ni][1]);
                s[ni][2] = __expf(s[ni][2]);
                s[ni][3] = __expf(s[ni][3]);
                rs0 += s[ni][0] + s[ni][1];
                rs1 += s[ni][2] + s[ni][3];
            }
            l0 += rs0;  l1 += rs1;

            // repack P accum frags -> A frags (bf16)
            uint32_t pf[4][4];
            #pragma unroll
            for (int kv = 0; kv < 4; ++kv) {
                pf[kv][0] = pack_bf16(s[2*kv][1],   s[2*kv][0]);
                pf[kv][1] = pack_bf16(s[2*kv][3],   s[2*kv][2]);
                pf[kv][2] = pack_bf16(s[2*kv+1][1], s[2*kv+1][0]);
                pf[kv][3] = pack_bf16(s[2*kv+1][3], s[2*kv+1][2]);
            }

            // O += P V  (V via ldmatrix.x4.trans)
            #pragma unroll
            for (int kv = 0; kv < 4; ++kv) {
                #pragma unroll
                for (int ndp = 0; ndp < 4; ++ndp) {
                    uint32_t v0, v1, v2, v3;
                    uint32_t off = (uint32_t)((kv * 16 + t_lrow) * 128 + ndp * 32 + t_hi);
                    ldm_x4t(v0, v1, v2, v3, suV + sw128(off));
                    mma_bf16(O[ndp*2],     pf[kv][0], pf[kv][1], pf[kv][2], pf[kv][3], v0, v1);
                    mma_bf16(O[ndp*2 + 1], pf[kv][0], pf[kv][1], pf[kv][2], pf[kv][3], v2, v3);
                }
            }
        }

        CP_WAIT0;
        __syncthreads();
    }

    // final row-sum reduction across the quad (lanes sharing a row: xor 1, 2)
    l0 += __shfl_xor_sync(0xffffffffu, l0, 1);
    l0 += __shfl_xor_sync(0xffffffffu, l0, 2);
    l1 += __shfl_xor_sync(0xffffffffu, l1, 1);
    l1 += __shfl_xor_sync(0xffffffffu, l1, 2);

    float inv0 = 1.f / l0, inv1 = 1.f / l1;
    int r0 = q0 + wid * 16 + g;
    #pragma unroll
    for (int nd = 0; nd < 8; ++nd) {
        int col = nd * 8 + tg * 2;
        *(uint32_t*)&g_attb[base + (size_t)r0 * D_MODEL + col] =
            pack_bf16(O[nd][1] * inv0, O[nd][0] * inv0);
        *(uint32_t*)&g_attb[base + (size_t)(r0 + 8) * D_MODEL + col] =
            pack_bf16(O[nd][3] * inv1, O[nd][2] * inv1);
    }
}

// ---------------- 4) final: low-pass reconstruct + LN + blend ----------------
__global__ __launch_bounds__(256) void final_kernel(
    const float* __restrict__ x, const float* __restrict__ sqb,
    const float* __restrict__ gam, const float* __restrict__ bet,
    float* __restrict__ out)
{
    __shared__ float red[8];
    int t = blockIdx.x, b = blockIdx.y;
    int tid = threadIdx.x;
    const float w = 2.f * PI_F / (float)SS;
    float sn, cn; sincosf(w * (float)t, &sn, &cn);
    float c2 = 2.f*cn*cn - 1.f, s2 = 2.f*sn*cn;

    size_t rowoff = ((size_t)b * SS + t) * D_MODEL;
    float y[4];
    float psum = 0.f;
    #pragma unroll
    for (int u = 0; u < 4; ++u) {
        int d  = tid + u * 256;
        int bd = b * D_MODEL + d;
        float low = (g_sums[0][bd]
                     + 2.f * (g_sums[1][bd]*cn + g_sums[2][bd]*sn)
                     + 2.f * (g_sums[3][bd]*c2 + g_sums[4][bd]*s2)) * (1.f/(float)SS);
        float be  = sqb[d];
        float b2v = be * be;
        float yv  = (1.f + b2v) * x[rowoff + d] + (1.f - b2v) * low;
        y[u] = yv; psum += yv;
    }
    #pragma unroll
    for (int o = 16; o > 0; o >>= 1) psum += __shfl_xor_sync(0xffffffffu, psum, o);
    if ((tid & 31) == 0) red[tid >> 5] = psum;
    __syncthreads();
    float tot = 0.f;
    #pragma unroll
    for (int k = 0; k < 8; ++k) tot += red[k];
    float mean = tot * (1.f/(float)D_MODEL);

    float vs = 0.f;
    #pragma unroll
    for (int u = 0; u < 4; ++u) { float dv = y[u] - mean; vs += dv * dv; }
    #pragma unroll
    for (int o = 16; o > 0; o >>= 1) vs += __shfl_xor_sync(0xffffffffu, vs, o);
    __syncthreads();
    if ((tid & 31) == 0) red[tid >> 5] = vs;
    __syncthreads();
    tot = 0.f;
    #pragma unroll
    for (int k = 0; k < 8; ++k) tot += red[k];
    float rstd = rsqrtf(tot * (1.f/(float)D_MODEL) + 1e-12f);

    #pragma unroll
    for (int u = 0; u < 4; ++u) {
        int d = tid + u * 256;
        float dsp = (y[u] - mean) * rstd * gam[d] + bet[d];
        out[rowoff + d] = 0.7f * dsp + 0.3f * __bfloat162float(g_attb[rowoff + d]);
    }
}

// ---------------- launch ----------------
extern "C" void kernel_launch(void* const* d_in, const int* in_sizes, int n_in,
                              void* d_out, int out_size) {
    const float* x   = (const float*)d_in[0];
    const float* sqb = (const float*)d_in[2];
    const float* gam = (const float*)d_in[3];
    const float* bet = (const float*)d_in[4];
    const float* qw  = (const float*)d_in[5];
    const float* qb  = (const float*)d_in[6];
    const float* kw  = (const float*)d_in[7];
    const float* kb  = (const float*)d_in[8];
    const float* vw  = (const float*)d_in[9];
    const float* vb  = (const float*)d_in[10];
    float* out = (float*)d_out;

    __nv_bfloat16 *pxb, *pwb, *pqb, *pkb, *pvb;
    cudaGetSymbolAddress((void**)&pxb, g_xb);
    cudaGetSymbolAddress((void**)&pwb, g_wb);
    cudaGetSymbolAddress((void**)&pqb, g_qb);
    cudaGetSymbolAddress((void**)&pkb, g_kb);
    cudaGetSymbolAddress((void**)&pvb, g_vb);
    cudaFuncSetAttribute(attn_mma_kernel, cudaFuncAttributeMaxDynamicSharedMemorySize, ATT_SMEM_BYTES);
    cudaFuncSetAttribute(gemm_mma_kernel, cudaFuncAttributeMaxDynamicSharedMemorySize, GEMM_SMEM_BYTES);

    dsp_sums_kernel<<<dim3(D_MODEL/256, BB, NSLICE), 256>>>(x);
    combine_sums_kernel<<<(5*BB*D_MODEL + 255)/256, 256>>>();

    // fp32 -> bf16 weight staging (one launch; x is fused into dsp_sums)
    cvtw_kernel<<<dim3((D_MODEL*D_MODEL)/2048, 3), 256>>>(qw, kw, vw, pwb);

    gemm_mma_kernel<<<dim3(D_MODEL/128, BS/256, 3), 512, GEMM_SMEM_BYTES>>>(
        pxb,
        pwb + 0*D_MODEL*D_MODEL, pwb + 1*D_MODEL*D_MODEL, pwb + 2*D_MODEL*D_MODEL,
        qb, kb, vb, pqb, pkb, pvb);

    attn_mma_kernel<<<dim3(SS/128, BB*NHEADS), 256, ATT_SMEM_BYTES>>>();

    final_kernel<<<dim3(SS, BB), 256>>>(x, sqb, gam, bet, out);
}